// round 5
// baseline (speedup 1.0000x reference)
#include <cuda_runtime.h>
#include <cstdint>

// GARCH(1,1) path generation, smem-staged, single-barrier software pipeline.
//
// R1: per-thread private rows -> L1tex wavefront bound (73.7%).
// R3: smem staging + coalesced cp.async/STG -> L1 26.9%, DRAM 52%, 254us.
//     Now latency-bound: 2 barriers + cp wait per stage, 8 warps/SM.
// R4: one barrier per stage; prefetch + previous-stage store issued before
//     the dependent compute chain; DEPTH 3 -> 4.
//
// sigma2_t = omega + sigma2_{t-1} * (alpha*z_{t-1}^2 + beta)
// x_t = mu + sqrt(max(sigma2_t, 1e-12)) * z_t

#define GARCH_N 32768
#define GARCH_T 2048
#define GARCH_D 2
#define ROW_BYTES (GARCH_T * GARCH_D * 4)   // 16384 bytes per chain

#define CH     128                 // chains per CTA (= threads per CTA)
#define TC     16                  // timesteps per stage
#define CHUNK  (TC * GARCH_D * 4)  // 128 bytes per chain per stage
#define NSTAGE (GARCH_T / TC)      // 128 stages
#define DEPTH  4                   // input pipeline depth

#define TILE_BYTES (CH * CHUNK)                       // 16 KB
#define SMEM_BYTES (TILE_BYTES * (DEPTH + 2))         // 4 in + 2 out = 96 KB

typedef unsigned long long u64;

__device__ __forceinline__ u64 pk2(float lo, float hi) {
    u64 r; asm("mov.b64 %0, {%1, %2};" : "=l"(r) : "f"(lo), "f"(hi)); return r;
}
__device__ __forceinline__ void upk2(u64 v, float& lo, float& hi) {
    asm("mov.b64 {%0, %1}, %2;" : "=f"(lo), "=f"(hi) : "l"(v));
}
__device__ __forceinline__ u64 fma2(u64 a, u64 b, u64 c) {
    u64 r; asm("fma.rn.f32x2 %0, %1, %2, %3;" : "=l"(r) : "l"(a), "l"(b), "l"(c)); return r;
}
__device__ __forceinline__ u64 mul2(u64 a, u64 b) {
    u64 r; asm("mul.rn.f32x2 %0, %1, %2;" : "=l"(r) : "l"(a), "l"(b)); return r;
}
__device__ __forceinline__ float sqapx(float x) {
    float r; asm("sqrt.approx.f32 %0, %1;" : "=f"(r) : "f"(x)); return r;
}

// byte offset of (chain c, 16B-chunk j) within a tile; XOR-8 swizzle keeps
// both the per-chain compute access (fixed c, j=0..7) and the cooperative
// access (8 lanes sweep j for one c) conflict-free for LDS/STS.128.
__device__ __forceinline__ int swz(int c, int j) {
    return c * CHUNK + ((j ^ (c & 7)) << 4);
}

__device__ __forceinline__ void cp_async16(char* smem_dst, const char* gsrc) {
    unsigned saddr = (unsigned)__cvta_generic_to_shared(smem_dst);
    asm volatile("cp.async.cg.shared.global [%0], [%1], 16;\n"
                 :: "r"(saddr), "l"(gsrc));
}
__device__ __forceinline__ void cp_commit() {
    asm volatile("cp.async.commit_group;\n");
}
__device__ __forceinline__ void cp_wait() {
    asm volatile("cp.async.wait_group %0;\n" :: "n"(DEPTH - 2));
}

__global__ void __launch_bounds__(CH, 2)
garch_kernel(const float* __restrict__ z,
             const float* __restrict__ omega,
             const float* __restrict__ alpha,
             const float* __restrict__ beta,
             const float* __restrict__ mu,
             const float* __restrict__ sigma2_0,
             float* __restrict__ x)
{
    extern __shared__ char smem[];
    char* inb[DEPTH];
#pragma unroll
    for (int i = 0; i < DEPTH; i++) inb[i] = smem + i * TILE_BYTES;
    char* outb0 = smem + DEPTH * TILE_BYTES;
    char* outb1 = outb0 + TILE_BYTES;

    const int tid = threadIdx.x;
    const size_t chain_base = (size_t)blockIdx.x * CH;
    const char* zg = (const char*)z + chain_base * ROW_BYTES;
    char*       xg = (char*)x       + chain_base * ROW_BYTES;

    // cooperative-transfer mapping: thread tid, round k -> chunk (c, j)
    // chunkid = tid + CH*k ; c = chunkid/8 ; j = chunkid%8
    // 8 consecutive lanes cover one chain's contiguous 128B (one line).

    // ---- prologue: fill DEPTH input stages; group g <-> tile g ----
#pragma unroll
    for (int sp = 0; sp < DEPTH; sp++) {
#pragma unroll
        for (int k = 0; k < 8; k++) {
            int chunkid = tid + CH * k;
            int c = chunkid >> 3, j = chunkid & 7;
            cp_async16(inb[sp] + swz(c, j),
                       zg + (size_t)c * ROW_BYTES + sp * CHUNK + j * 16);
        }
        cp_commit();
    }

    // ---- per-chain recurrence state ----
    const u64 om2 = pk2(omega[0], omega[1]);
    const u64 al2 = pk2(alpha[0], alpha[1]);
    const u64 be2 = pk2(beta[0], beta[1]);
    const float m0 = mu[0], m1 = mu[1];
    u64 s2 = pk2(sigma2_0[0], sigma2_0[1]);
    u64 fc = be2;

    for (int s = 0; s < NSTAGE; s++) {
        // Group accounting: before this wait, committed groups are
        // 0..DEPTH+s-2 (prologue + one per previous loop iter). Waiting for
        // pending <= DEPTH-2 drains through group s -> tile s resident.
        cp_wait();
        // One barrier covers: (a) tile s visible to all threads, (b) buffer
        // inb[(s-1)%DEPTH] fully consumed (in iter s-1), (c) out tile
        // ob[(s-1)&1] fully written (in iter s-1).
        __syncthreads();

        // ---- prefetch tile s+DEPTH-1 into the buffer freed at iter s-1 ----
        if (s > 0) {
            const int sp = s + DEPTH - 1;
            if (sp < NSTAGE) {
                char* dst = inb[sp % DEPTH];    // == inb[(s-1) % DEPTH]
#pragma unroll
                for (int k = 0; k < 8; k++) {
                    int chunkid = tid + CH * k;
                    int c = chunkid >> 3, j = chunkid & 7;
                    cp_async16(dst + swz(c, j),
                               zg + (size_t)c * ROW_BYTES + (size_t)sp * CHUNK + j * 16);
                }
            }
            cp_commit();   // commit every iter s>=1 (empty at tail is fine)
        }

        // ---- cooperative coalesced store of out tile from stage s-1 ----
        if (s > 0) {
            const char* ob = ((s - 1) & 1) ? outb1 : outb0;
            const size_t tbase = (size_t)(s - 1) * CHUNK;
#pragma unroll
            for (int k = 0; k < 8; k++) {
                int chunkid = tid + CH * k;
                int c = chunkid >> 3, j = chunkid & 7;
                const float4 v = *(const float4*)(ob + swz(c, j));
                *(float4*)(xg + (size_t)c * ROW_BYTES + tbase + j * 16) = v;
            }
        }

        // ---- compute 16 timesteps for this thread's chain ----
        const char* ib = inb[s % DEPTH];
        char* ob = (s & 1) ? outb1 : outb0;
#pragma unroll
        for (int j = 0; j < 8; j++) {
            const float4 za = *(const float4*)(ib + swz(tid, j));
            float4 xa;
#define GSTEP(z0, z1, o0, o1)                                        \
            {                                                        \
                s2 = fma2(s2, fc, om2);                              \
                float lo, hi;                                        \
                upk2(s2, lo, hi);                                    \
                lo = fmaxf(lo, 1e-12f);                              \
                hi = fmaxf(hi, 1e-12f);                              \
                s2 = pk2(lo, hi);                                    \
                const u64 zz = pk2(z0, z1);                          \
                fc = fma2(al2, mul2(zz, zz), be2);                   \
                o0 = fmaf(sqapx(lo), (z0), m0);                      \
                o1 = fmaf(sqapx(hi), (z1), m1);                      \
            }
            GSTEP(za.x, za.y, xa.x, xa.y)
            GSTEP(za.z, za.w, xa.z, xa.w)
#undef GSTEP
            *(float4*)(ob + swz(tid, j)) = xa;
        }
    }

    // ---- epilogue: store the final out tile ----
    __syncthreads();
    {
        const char* ob = ((NSTAGE - 1) & 1) ? outb1 : outb0;
        const size_t tbase = (size_t)(NSTAGE - 1) * CHUNK;
#pragma unroll
        for (int k = 0; k < 8; k++) {
            int chunkid = tid + CH * k;
            int c = chunkid >> 3, j = chunkid & 7;
            const float4 v = *(const float4*)(ob + swz(c, j));
            *(float4*)(xg + (size_t)c * ROW_BYTES + tbase + j * 16) = v;
        }
    }
}

extern "C" void kernel_launch(void* const* d_in, const int* in_sizes, int n_in,
                              void* d_out, int out_size)
{
    const float* z        = (const float*)d_in[0];
    const float* omega    = (const float*)d_in[1];
    const float* alpha    = (const float*)d_in[2];
    const float* beta     = (const float*)d_in[3];
    const float* mu       = (const float*)d_in[4];
    const float* sigma2_0 = (const float*)d_in[5];
    float* x = (float*)d_out;

    cudaFuncSetAttribute(garch_kernel,
                         cudaFuncAttributeMaxDynamicSharedMemorySize, SMEM_BYTES);

    const int blocks = GARCH_N / CH;   // 256
    garch_kernel<<<blocks, CH, SMEM_BYTES>>>(z, omega, alpha, beta, mu, sigma2_0, x);
}

// round 6
// speedup vs baseline: 1.2845x; 1.2845x over previous
#include <cuda_runtime.h>
#include <cstdint>

// GARCH(1,1) path generation — warp-autonomous smem pipelines.
//
// History: R1 private rows -> L1tex wavefront bound (302us). R3 CTA-wide smem
// staging -> 254us, DRAM 52%. R4 single CTA barrier -> no change: bound is
// cross-warp lockstep at fixed-low occupancy (1024 warps total = 6.9/SM).
// R5: each warp owns 32 chains + private smem ring (5 in + 2 out tiles),
// warp-internal cooperative transfers, only __syncwarp. DEPTH=5 prefetch.
//
// sigma2_t = omega + sigma2_{t-1} * (alpha*z_{t-1}^2 + beta)
// x_t = mu + sqrt(max(sigma2_t, 1e-12)) * z_t

#define GARCH_N 32768
#define GARCH_T 2048
#define GARCH_D 2
#define ROW_BYTES (GARCH_T * GARCH_D * 4)   // 16384 bytes per chain

#define CH      128                // chains per CTA (= threads)
#define WARPS   4
#define CHW     32                 // chains per warp
#define TC      16                 // timesteps per stage
#define CHUNK   (TC * GARCH_D * 4) // 128 bytes per chain per stage
#define NSTAGE  (GARCH_T / TC)     // 128 stages
#define DEPTH   5                  // input ring depth (per warp)

#define TILE_W  (CHW * CHUNK)                    // 4 KB per warp-tile
#define WSEG    (TILE_W * (DEPTH + 2))           // 28 KB per warp
#define SMEM_BYTES (WSEG * WARPS)                // 112 KB per CTA

typedef unsigned long long u64;

__device__ __forceinline__ u64 pk2(float lo, float hi) {
    u64 r; asm("mov.b64 %0, {%1, %2};" : "=l"(r) : "f"(lo), "f"(hi)); return r;
}
__device__ __forceinline__ void upk2(u64 v, float& lo, float& hi) {
    asm("mov.b64 {%0, %1}, %2;" : "=f"(lo), "=f"(hi) : "l"(v));
}
__device__ __forceinline__ u64 fma2(u64 a, u64 b, u64 c) {
    u64 r; asm("fma.rn.f32x2 %0, %1, %2, %3;" : "=l"(r) : "l"(a), "l"(b), "l"(c)); return r;
}
__device__ __forceinline__ u64 mul2(u64 a, u64 b) {
    u64 r; asm("mul.rn.f32x2 %0, %1, %2;" : "=l"(r) : "l"(a), "l"(b)); return r;
}
__device__ __forceinline__ float sqapx(float x) {
    float r; asm("sqrt.approx.f32 %0, %1;" : "=f"(r) : "f"(x)); return r;
}

// offset of (local chain c, 16B-chunk j) within a 4KB warp-tile.
// XOR-8 swizzle: conflict-free for both the per-chain access (fixed c,
// j=0..7) and the cooperative access (8 lanes sweep the row of one c).
__device__ __forceinline__ int swz(int c, int j) {
    return c * CHUNK + ((j ^ (c & 7)) << 4);
}

__device__ __forceinline__ void cp_async16(char* smem_dst, const char* gsrc) {
    unsigned saddr = (unsigned)__cvta_generic_to_shared(smem_dst);
    asm volatile("cp.async.cg.shared.global [%0], [%1], 16;\n"
                 :: "r"(saddr), "l"(gsrc));
}
__device__ __forceinline__ void cp_commit() {
    asm volatile("cp.async.commit_group;\n");
}
__device__ __forceinline__ void cp_wait() {
    asm volatile("cp.async.wait_group %0;\n" :: "n"(DEPTH - 1));
}

__global__ void __launch_bounds__(CH, 2)
garch_kernel(const float* __restrict__ z,
             const float* __restrict__ omega,
             const float* __restrict__ alpha,
             const float* __restrict__ beta,
             const float* __restrict__ mu,
             const float* __restrict__ sigma2_0,
             float* __restrict__ x)
{
    extern __shared__ char smem[];
    const int tid = threadIdx.x;
    const int w   = tid >> 5;
    const int l   = tid & 31;

    char* wbase = smem + w * WSEG;          // this warp's private segment
    char* outb0 = wbase + DEPTH * TILE_W;
    char* outb1 = outb0 + TILE_W;

    const size_t chain_base = (size_t)blockIdx.x * CH + (size_t)w * CHW;
    const char* zg = (const char*)z + chain_base * ROW_BYTES;
    char*       xg = (char*)x       + chain_base * ROW_BYTES;

    // warp-internal cooperative mapping: round k (0..7):
    //   chunkid = l + 32k ; local chain c = chunkid>>3 ; j = l&7 (fixed)
    // 8 consecutive lanes cover one chain's contiguous 128B (one line).
    const int jj = l & 7;

    // ---- prologue: fill DEPTH input tiles; group g <-> tile g ----
#pragma unroll
    for (int sp = 0; sp < DEPTH; sp++) {
        char* dst = wbase + sp * TILE_W;
#pragma unroll
        for (int k = 0; k < 8; k++) {
            int c = (l + 32 * k) >> 3;
            cp_async16(dst + swz(c, jj),
                       zg + (size_t)c * ROW_BYTES + sp * CHUNK + jj * 16);
        }
        cp_commit();
    }

    // ---- per-chain recurrence state ----
    const u64 om2 = pk2(omega[0], omega[1]);
    const u64 al2 = pk2(alpha[0], alpha[1]);
    const u64 be2 = pk2(beta[0], beta[1]);
    const float m0 = mu[0], m1 = mu[1];
    u64 s2 = pk2(sigma2_0[0], sigma2_0[1]);
    u64 fc = be2;

    for (int s = 0; s < NSTAGE; s++) {
        // ---- prefetch tile s+DEPTH-1 into ring slot freed at iter s-1 ----
        if (s > 0) {
            const int sp = s + DEPTH - 1;
            if (sp < NSTAGE) {
                char* dst = wbase + (sp % DEPTH) * TILE_W;
#pragma unroll
                for (int k = 0; k < 8; k++) {
                    int c = (l + 32 * k) >> 3;
                    cp_async16(dst + swz(c, jj),
                               zg + (size_t)c * ROW_BYTES + (size_t)sp * CHUNK + jj * 16);
                }
            }
            cp_commit();   // always commit: keeps group<->tile accounting exact
        }

        // ---- cooperative coalesced store of out tile s-1 ----
        if (s > 0) {
            const char* ob = ((s - 1) & 1) ? outb1 : outb0;
            const size_t tbase = (size_t)(s - 1) * CHUNK;
#pragma unroll
            for (int k = 0; k < 8; k++) {
                int c = (l + 32 * k) >> 3;
                const float4 v = *(const float4*)(ob + swz(c, jj));
                *(float4*)(xg + (size_t)c * ROW_BYTES + tbase + jj * 16) = v;
            }
        }

        // Groups committed so far: DEPTH + s (minus none; tail commits may be
        // empty and complete instantly). pending<=DEPTH-1 => tile s complete.
        cp_wait();
        __syncwarp();   // make lane-X cp.async data visible warp-wide

        // ---- compute 16 timesteps for this thread's chain (= lane l) ----
        const char* ib = wbase + (s % DEPTH) * TILE_W;
        char* ob = (s & 1) ? outb1 : outb0;
#pragma unroll
        for (int j = 0; j < 8; j++) {
            const float4 za = *(const float4*)(ib + swz(l, j));
            float4 xa;
#define GSTEP(z0, z1, o0, o1)                                        \
            {                                                        \
                s2 = fma2(s2, fc, om2);                              \
                float lo, hi;                                        \
                upk2(s2, lo, hi);                                    \
                lo = fmaxf(lo, 1e-12f);                              \
                hi = fmaxf(hi, 1e-12f);                              \
                s2 = pk2(lo, hi);                                    \
                const u64 zz = pk2(z0, z1);                          \
                fc = fma2(al2, mul2(zz, zz), be2);                   \
                o0 = fmaf(sqapx(lo), (z0), m0);                      \
                o1 = fmaf(sqapx(hi), (z1), m1);                      \
            }
            GSTEP(za.x, za.y, xa.x, xa.y)
            GSTEP(za.z, za.w, xa.z, xa.w)
#undef GSTEP
            *(float4*)(ob + swz(l, j)) = xa;
        }

        __syncwarp();   // out tile s complete before iter s+1 reads it
    }

    // ---- epilogue: store the final out tile ----
    {
        const char* ob = ((NSTAGE - 1) & 1) ? outb1 : outb0;
        const size_t tbase = (size_t)(NSTAGE - 1) * CHUNK;
#pragma unroll
        for (int k = 0; k < 8; k++) {
            int c = (l + 32 * k) >> 3;
            const float4 v = *(const float4*)(ob + swz(c, jj));
            *(float4*)(xg + (size_t)c * ROW_BYTES + tbase + jj * 16) = v;
        }
    }
}

extern "C" void kernel_launch(void* const* d_in, const int* in_sizes, int n_in,
                              void* d_out, int out_size)
{
    const float* z        = (const float*)d_in[0];
    const float* omega    = (const float*)d_in[1];
    const float* alpha    = (const float*)d_in[2];
    const float* beta     = (const float*)d_in[3];
    const float* mu       = (const float*)d_in[4];
    const float* sigma2_0 = (const float*)d_in[5];
    float* x = (float*)d_out;

    cudaFuncSetAttribute(garch_kernel,
                         cudaFuncAttributeMaxDynamicSharedMemorySize, SMEM_BYTES);

    const int blocks = GARCH_N / CH;   // 256
    garch_kernel<<<blocks, CH, SMEM_BYTES>>>(z, omega, alpha, beta, mu, sigma2_0, x);
}

// round 7
// speedup vs baseline: 1.3449x; 1.0470x over previous
#include <cuda_runtime.h>
#include <cstdint>

// GARCH(1,1) path generation — single-warp CTAs, warp-autonomous pipelines.
//
// History: R1 private rows -> L1tex wavefront bound (302us). R3 CTA smem
// staging (254us). R5 warp-autonomous rings, syncwarp-only -> 204us,
// DRAM 69.6%. R6: CTA == warp (CH=32, grid=1024). 256x112KB CTAs packed
// 2/SM and left a 16% wave-imbalance tax (108 SMs ran 2 CTAs, 40 ran 1).
// 1024x28KB CTAs pack 6-7/SM across all 148 SMs (~1% imbalance).
//
// sigma2_t = omega + sigma2_{t-1} * (alpha*z_{t-1}^2 + beta)
// x_t = mu + sqrt(max(sigma2_t, 1e-12)) * z_t

#define GARCH_N 32768
#define GARCH_T 2048
#define GARCH_D 2
#define ROW_BYTES (GARCH_T * GARCH_D * 4)   // 16384 bytes per chain

#define CH      32                 // chains per CTA (= threads = 1 warp)
#define TC      16                 // timesteps per stage
#define CHUNK   (TC * GARCH_D * 4) // 128 bytes per chain per stage
#define NSTAGE  (GARCH_T / TC)     // 128 stages
#define DEPTH   5                  // input ring depth

#define TILE_W  (CH * CHUNK)                     // 4 KB per tile
#define SMEM_BYTES (TILE_W * (DEPTH + 2))        // 5 in + 2 out = 28 KB

typedef unsigned long long u64;

__device__ __forceinline__ u64 pk2(float lo, float hi) {
    u64 r; asm("mov.b64 %0, {%1, %2};" : "=l"(r) : "f"(lo), "f"(hi)); return r;
}
__device__ __forceinline__ void upk2(u64 v, float& lo, float& hi) {
    asm("mov.b64 {%0, %1}, %2;" : "=f"(lo), "=f"(hi) : "l"(v));
}
__device__ __forceinline__ u64 fma2(u64 a, u64 b, u64 c) {
    u64 r; asm("fma.rn.f32x2 %0, %1, %2, %3;" : "=l"(r) : "l"(a), "l"(b), "l"(c)); return r;
}
__device__ __forceinline__ u64 mul2(u64 a, u64 b) {
    u64 r; asm("mul.rn.f32x2 %0, %1, %2;" : "=l"(r) : "l"(a), "l"(b)); return r;
}
__device__ __forceinline__ float sqapx(float x) {
    float r; asm("sqrt.approx.f32 %0, %1;" : "=f"(r) : "f"(x)); return r;
}

// offset of (local chain c, 16B-chunk j) within a 4KB tile.
// XOR-8 swizzle: conflict-free for both the per-chain access (fixed c,
// j=0..7) and the cooperative access (8 lanes sweep the row of one c).
__device__ __forceinline__ int swz(int c, int j) {
    return c * CHUNK + ((j ^ (c & 7)) << 4);
}

__device__ __forceinline__ void cp_async16(char* smem_dst, const char* gsrc) {
    unsigned saddr = (unsigned)__cvta_generic_to_shared(smem_dst);
    asm volatile("cp.async.cg.shared.global [%0], [%1], 16;\n"
                 :: "r"(saddr), "l"(gsrc));
}
__device__ __forceinline__ void cp_commit() {
    asm volatile("cp.async.commit_group;\n");
}
__device__ __forceinline__ void cp_wait() {
    asm volatile("cp.async.wait_group %0;\n" :: "n"(DEPTH - 1));
}

__global__ void __launch_bounds__(CH, 8)
garch_kernel(const float* __restrict__ z,
             const float* __restrict__ omega,
             const float* __restrict__ alpha,
             const float* __restrict__ beta,
             const float* __restrict__ mu,
             const float* __restrict__ sigma2_0,
             float* __restrict__ x)
{
    extern __shared__ char smem[];
    const int l = threadIdx.x;              // lane

    char* wbase = smem;
    char* outb0 = wbase + DEPTH * TILE_W;
    char* outb1 = outb0 + TILE_W;

    const size_t chain_base = (size_t)blockIdx.x * CH;
    const char* zg = (const char*)z + chain_base * ROW_BYTES;
    char*       xg = (char*)x       + chain_base * ROW_BYTES;

    // warp-internal cooperative mapping: round k (0..7):
    //   chunkid = l + 32k ; local chain c = chunkid>>3 ; j = l&7 (fixed)
    // 8 consecutive lanes cover one chain's contiguous 128B (one line).
    const int jj = l & 7;

    // ---- prologue: fill DEPTH input tiles; group g <-> tile g ----
#pragma unroll
    for (int sp = 0; sp < DEPTH; sp++) {
        char* dst = wbase + sp * TILE_W;
#pragma unroll
        for (int k = 0; k < 8; k++) {
            int c = (l + 32 * k) >> 3;
            cp_async16(dst + swz(c, jj),
                       zg + (size_t)c * ROW_BYTES + sp * CHUNK + jj * 16);
        }
        cp_commit();
    }

    // ---- per-chain recurrence state ----
    const u64 om2 = pk2(omega[0], omega[1]);
    const u64 al2 = pk2(alpha[0], alpha[1]);
    const u64 be2 = pk2(beta[0], beta[1]);
    const float m0 = mu[0], m1 = mu[1];
    u64 s2 = pk2(sigma2_0[0], sigma2_0[1]);
    u64 fc = be2;

    for (int s = 0; s < NSTAGE; s++) {
        // ---- prefetch tile s+DEPTH-1 into ring slot freed at iter s-1 ----
        if (s > 0) {
            const int sp = s + DEPTH - 1;
            if (sp < NSTAGE) {
                char* dst = wbase + (sp % DEPTH) * TILE_W;
#pragma unroll
                for (int k = 0; k < 8; k++) {
                    int c = (l + 32 * k) >> 3;
                    cp_async16(dst + swz(c, jj),
                               zg + (size_t)c * ROW_BYTES + (size_t)sp * CHUNK + jj * 16);
                }
            }
            cp_commit();   // always commit: keeps group<->tile accounting exact
        }

        // ---- cooperative coalesced store of out tile s-1 ----
        if (s > 0) {
            const char* ob = ((s - 1) & 1) ? outb1 : outb0;
            const size_t tbase = (size_t)(s - 1) * CHUNK;
#pragma unroll
            for (int k = 0; k < 8; k++) {
                int c = (l + 32 * k) >> 3;
                const float4 v = *(const float4*)(ob + swz(c, jj));
                *(float4*)(xg + (size_t)c * ROW_BYTES + tbase + jj * 16) = v;
            }
        }

        // Groups committed so far: DEPTH + s (tail commits may be empty and
        // complete instantly). pending<=DEPTH-1 => tile s complete.
        cp_wait();
        __syncwarp();   // make lane-X cp.async data visible warp-wide

        // ---- compute 16 timesteps for this thread's chain (= lane l) ----
        const char* ib = wbase + (s % DEPTH) * TILE_W;
        char* ob = (s & 1) ? outb1 : outb0;
#pragma unroll
        for (int j = 0; j < 8; j++) {
            const float4 za = *(const float4*)(ib + swz(l, j));
            float4 xa;
#define GSTEP(z0, z1, o0, o1)                                        \
            {                                                        \
                s2 = fma2(s2, fc, om2);                              \
                float lo, hi;                                        \
                upk2(s2, lo, hi);                                    \
                lo = fmaxf(lo, 1e-12f);                              \
                hi = fmaxf(hi, 1e-12f);                              \
                s2 = pk2(lo, hi);                                    \
                const u64 zz = pk2(z0, z1);                          \
                fc = fma2(al2, mul2(zz, zz), be2);                   \
                o0 = fmaf(sqapx(lo), (z0), m0);                      \
                o1 = fmaf(sqapx(hi), (z1), m1);                      \
            }
            GSTEP(za.x, za.y, xa.x, xa.y)
            GSTEP(za.z, za.w, xa.z, xa.w)
#undef GSTEP
            *(float4*)(ob + swz(l, j)) = xa;
        }

        __syncwarp();   // out tile s complete before iter s+1 reads it
    }

    // ---- epilogue: store the final out tile ----
    {
        const char* ob = ((NSTAGE - 1) & 1) ? outb1 : outb0;
        const size_t tbase = (size_t)(NSTAGE - 1) * CHUNK;
#pragma unroll
        for (int k = 0; k < 8; k++) {
            int c = (l + 32 * k) >> 3;
            const float4 v = *(const float4*)(ob + swz(c, jj));
            *(float4*)(xg + (size_t)c * ROW_BYTES + tbase + jj * 16) = v;
        }
    }
}

extern "C" void kernel_launch(void* const* d_in, const int* in_sizes, int n_in,
                              void* d_out, int out_size)
{
    const float* z        = (const float*)d_in[0];
    const float* omega    = (const float*)d_in[1];
    const float* alpha    = (const float*)d_in[2];
    const float* beta     = (const float*)d_in[3];
    const float* mu       = (const float*)d_in[4];
    const float* sigma2_0 = (const float*)d_in[5];
    float* x = (float*)d_out;

    cudaFuncSetAttribute(garch_kernel,
                         cudaFuncAttributeMaxDynamicSharedMemorySize, SMEM_BYTES);

    const int blocks = GARCH_N / CH;   // 1024 single-warp CTAs
    garch_kernel<<<blocks, CH, SMEM_BYTES>>>(z, omega, alpha, beta, mu, sigma2_0, x);
}